// round 12
// baseline (speedup 1.0000x reference)
#include <cuda_runtime.h>
#include <cuda_fp16.h>

// 2-layer GCN. ELL adjacency (cap 128), rows padded to multiple of 8 with a
// dummy zero node (index NN) -> branch-free gather inner loops. Layer1
// propagates 13-ch input (64B rows); MLP applied post-aggregation in its own
// thread-per-node kernel. NPW=8 for degree smoothing.
#define NN 100000
#define NE 3200000
#define C0 13
#define C0P 16
#define C1 32
#define C2 16
#define CAP 128
#define NPW 8   // nodes per warp in gather kernels

#define ADDX2(a, b) asm("add.rn.f32x2 %0, %1, %2;" : "=l"(a) : "l"(a), "l"(b))

__device__ int    g_cur[NN];
__device__ int    g_ell[NN * CAP];
__device__ float  g_dinv[NN];
// Row NN is the dummy row: NEVER written, stays 0 from static zero-init.
__device__ __align__(16) float g_g0[(NN + 1) * C0P];  // x * dinv, padded 16 ch
__device__ __align__(16) float g_agg[NN * C0P];       // dinv * (sum + self)
__device__ __align__(16) float g_g2[(NN + 1) * C2];   // (h W2) * dinv
__device__ int    g_odd_nonzero;

// ---------------- init: zero counters + detect int64 vs int32 ----------------
__global__ void k_init(const unsigned* __restrict__ p, int n, int E) {
    int i = blockIdx.x * blockDim.x + threadIdx.x;
    if (i < n) g_cur[i] = 0;
    if (blockIdx.x == 0) {
        if (threadIdx.x == 0) g_odd_nonzero = 0;
        __syncthreads();
        int pairs = E < 2048 ? E : 2048;
        int any = 0;
        for (int j = threadIdx.x; j < pairs; j += blockDim.x)
            if (p[2 * j + 1] != 0u) any = 1;
        if (any) atomicOr(&g_odd_nonzero, 1);
    }
}

// ---------------- build ELL + degree: 2 edges/thread, 16B index loads ----------------
__global__ void k_fill(const void* __restrict__ p, int E) {
    int i = blockIdx.x * blockDim.x + threadIdx.x;   // handles edges 2i, 2i+1
    int e0 = 2 * i;
    if (e0 >= E) return;
    int has2 = (e0 + 1 < E);
    int s0, s1, d0, d1;
    if (g_odd_nonzero == 0) {                        // int64 input
        const long long* q = (const long long*)p;
        longlong2 ts = ((const longlong2*)q)[i];
        longlong2 td = *(const longlong2*)(q + E + e0);
        s0 = (int)ts.x; s1 = (int)ts.y;
        d0 = (int)td.x; d1 = (int)td.y;
    } else {                                          // int32 input
        const int* q = (const int*)p;
        int2 ts = ((const int2*)q)[i];
        int2 td = *(const int2*)(q + E + e0);
        s0 = ts.x; s1 = ts.y;
        d0 = td.x; d1 = td.y;
    }
    int pos0 = atomicAdd(&g_cur[d0], 1);
    if (pos0 < CAP) g_ell[d0 * CAP + pos0] = s0;
    if (has2) {
        int pos1 = atomicAdd(&g_cur[d1], 1);
        if (pos1 < CAP) g_ell[d1 * CAP + pos1] = s1;
    }
}

// ---------------- scale0: g0 = pad16(x) * dinv; dinv; ELL row padding ----------------
__global__ void k_scale0(const float* __restrict__ x, int n) {
    int t = blockIdx.x * blockDim.x + threadIdx.x;   // 4 threads per node
    int node = t >> 2, co = t & 3;
    if (node >= n) return;
    int deg = g_cur[node];
    float di = rsqrtf((float)(deg + 1));
    if (co == 0) g_dinv[node] = di;
    // pad ELL row to multiple of 8 with dummy index NN (zero row)
    if (deg < CAP) {
        int deg8 = (deg + 7) & ~7;
        if (deg8 > CAP) deg8 = CAP;
        for (int ppos = deg + co; ppos < deg8; ppos += 4)
            g_ell[node * CAP + ppos] = NN;
    }
    float4 v;
    const float* xr = x + node * C0;
    int c = 4 * co;
    v.x = (c     < C0) ? xr[c]     * di : 0.0f;
    v.y = (c + 1 < C0) ? xr[c + 1] * di : 0.0f;
    v.z = (c + 2 < C0) ? xr[c + 2] * di : 0.0f;
    v.w = (c + 3 < C0) ? xr[c + 3] * di : 0.0f;
    ((float4*)g_g0)[node * 4 + co] = v;
}

// ---------------- gather1: agg[node] = dinv * (sum_in g0[src] + g0[node]) ----------------
__global__ void __launch_bounds__(256, 8)
k_gather1(int n) {
    int warp = threadIdx.x >> 5, lane = threadIdx.x & 31;
    int grp = lane >> 2;      // edge subgroup 0..7
    int co  = lane & 3;       // 16B column (4 x float4 = 16 ch)
    const ulonglong2* __restrict__ g0v = (const ulonglong2*)g_g0;  // 4 per row

    int node0 = (blockIdx.x * 8 + warp) * NPW;
    int node1 = node0 + NPW; if (node1 > n) node1 = n;
    for (int node = node0; node < node1; node++) {
        int deg = g_cur[node]; if (deg > CAP) deg = CAP;
        int deg8 = (deg + 7) & ~7;
        unsigned long long a0 = 0ULL, a1 = 0ULL;
        if (grp == 0) {                       // self loop
            ulonglong2 t = g0v[node * 4 + co];
            a0 = t.x; a1 = t.y;
        }
        const int* __restrict__ row = &g_ell[node * CAP];
        for (int j0 = 0; j0 < deg8; j0 += 32) {
            int base = row[j0 + lane] * 4;    // no clamp: in-bounds, pads are zero-row
            int m = deg8 - j0;
            if (m >= 32) {
                #pragma unroll
                for (int k = 0; k < 4; k++) {
                    int b = __shfl_sync(~0u, base, 8 * k + grp);
                    ulonglong2 t = g0v[b + co];
                    ADDX2(a0, t.x); ADDX2(a1, t.y);
                }
            } else {
                int kmax = m >> 3;            // uniform, branch-free body
                for (int k = 0; k < kmax; k++) {
                    int b = __shfl_sync(~0u, base, 8 * k + grp);
                    ulonglong2 t = g0v[b + co];
                    ADDX2(a0, t.x); ADDX2(a1, t.y);
                }
            }
        }
        float f0, f1, f2, f3;
        asm("mov.b64 {%0,%1}, %2;" : "=f"(f0), "=f"(f1) : "l"(a0));
        asm("mov.b64 {%0,%1}, %2;" : "=f"(f2), "=f"(f3) : "l"(a1));
        #pragma unroll
        for (int o = 4; o <= 16; o <<= 1) {
            f0 += __shfl_xor_sync(~0u, f0, o);
            f1 += __shfl_xor_sync(~0u, f1, o);
            f2 += __shfl_xor_sync(~0u, f2, o);
            f3 += __shfl_xor_sync(~0u, f3, o);
        }
        if (lane < 4) {
            float di = g_dinv[node];
            float4 a;
            a.x = f0 * di; a.y = f1 * di; a.z = f2 * di; a.w = f3 * di;
            ((float4*)g_agg)[node * 4 + co] = a;
        }
    }
}

// ---------------- mlp: g2[node] = dinv * (relu(agg W1 + b1) W2), thread/node ----------------
__global__ void k_mlp(const float* __restrict__ W1, const float* __restrict__ b1,
                      const float* __restrict__ W2, int n) {
    __shared__ __align__(16) float sW1T[C1 * C0P];   // [c][k], k padded to 16, zeros
    __shared__ __align__(16) float sW2[C1 * C2];     // [c][j]
    __shared__ float sb1[C1];
    for (int i = threadIdx.x; i < C1 * C0P; i += blockDim.x) {
        int c = i >> 4, k = i & 15;
        sW1T[i] = (k < C0) ? W1[k * C1 + c] : 0.0f;
    }
    for (int i = threadIdx.x; i < C1 * C2; i += blockDim.x) sW2[i] = W2[i];
    if (threadIdx.x < C1) sb1[threadIdx.x] = b1[threadIdx.x];
    __syncthreads();
    int node = blockIdx.x * blockDim.x + threadIdx.x;
    if (node >= n) return;
    const float4* av = &((const float4*)g_agg)[node * 4];
    float4 A0 = av[0], A1 = av[1], A2 = av[2], A3 = av[3];
    float di = g_dinv[node];
    float o[C2];
    #pragma unroll
    for (int j = 0; j < C2; j++) o[j] = 0.0f;
    #pragma unroll
    for (int c = 0; c < C1; c++) {
        const float4* wt = (const float4*)&sW1T[c * C0P];
        float4 w0 = wt[0], w1 = wt[1], w2 = wt[2], w3 = wt[3];
        float h = sb1[c];
        h = fmaf(A0.x, w0.x, h); h = fmaf(A0.y, w0.y, h);
        h = fmaf(A0.z, w0.z, h); h = fmaf(A0.w, w0.w, h);
        h = fmaf(A1.x, w1.x, h); h = fmaf(A1.y, w1.y, h);
        h = fmaf(A1.z, w1.z, h); h = fmaf(A1.w, w1.w, h);
        h = fmaf(A2.x, w2.x, h); h = fmaf(A2.y, w2.y, h);
        h = fmaf(A2.z, w2.z, h); h = fmaf(A2.w, w2.w, h);
        h = fmaf(A3.x, w3.x, h);
        h = fmaxf(h, 0.0f);
        const float4* wu = (const float4*)&sW2[c * C2];
        float4 u0 = wu[0], u1 = wu[1], u2 = wu[2], u3 = wu[3];
        o[0]  = fmaf(h, u0.x, o[0]);  o[1]  = fmaf(h, u0.y, o[1]);
        o[2]  = fmaf(h, u0.z, o[2]);  o[3]  = fmaf(h, u0.w, o[3]);
        o[4]  = fmaf(h, u1.x, o[4]);  o[5]  = fmaf(h, u1.y, o[5]);
        o[6]  = fmaf(h, u1.z, o[6]);  o[7]  = fmaf(h, u1.w, o[7]);
        o[8]  = fmaf(h, u2.x, o[8]);  o[9]  = fmaf(h, u2.y, o[9]);
        o[10] = fmaf(h, u2.z, o[10]); o[11] = fmaf(h, u2.w, o[11]);
        o[12] = fmaf(h, u3.x, o[12]); o[13] = fmaf(h, u3.y, o[13]);
        o[14] = fmaf(h, u3.z, o[14]); o[15] = fmaf(h, u3.w, o[15]);
    }
    float4* ov = &((float4*)g_g2)[node * 4];
    #pragma unroll
    for (int q = 0; q < 4; q++) {
        float4 r;
        r.x = o[4 * q + 0] * di; r.y = o[4 * q + 1] * di;
        r.z = o[4 * q + 2] * di; r.w = o[4 * q + 3] * di;
        ov[q] = r;
    }
}

// ---------------- layer2 gather + bias -> out ----------------
__global__ void __launch_bounds__(256, 8)
k_layer2(float* __restrict__ out, const float* __restrict__ b2, int n) {
    int warp = threadIdx.x >> 5, lane = threadIdx.x & 31;
    int grp = lane >> 2;      // edge subgroup 0..7
    int co  = lane & 3;       // 16B column (4 x float4 = 16 ch)
    const ulonglong2* __restrict__ g2v = (const ulonglong2*)g_g2;  // 4 per row

    int node0 = (blockIdx.x * 8 + warp) * NPW;
    int node1 = node0 + NPW; if (node1 > n) node1 = n;
    for (int node = node0; node < node1; node++) {
        int deg = g_cur[node]; if (deg > CAP) deg = CAP;
        int deg8 = (deg + 7) & ~7;
        unsigned long long a0 = 0ULL, a1 = 0ULL;
        if (grp == 0) {                       // self loop
            ulonglong2 t = g2v[node * 4 + co];
            a0 = t.x; a1 = t.y;
        }
        const int* __restrict__ row = &g_ell[node * CAP];
        for (int j0 = 0; j0 < deg8; j0 += 32) {
            int base = row[j0 + lane] * 4;
            int m = deg8 - j0;
            if (m >= 32) {
                #pragma unroll
                for (int k = 0; k < 4; k++) {
                    int b = __shfl_sync(~0u, base, 8 * k + grp);
                    ulonglong2 t = g2v[b + co];
                    ADDX2(a0, t.x); ADDX2(a1, t.y);
                }
            } else {
                int kmax = m >> 3;
                for (int k = 0; k < kmax; k++) {
                    int b = __shfl_sync(~0u, base, 8 * k + grp);
                    ulonglong2 t = g2v[b + co];
                    ADDX2(a0, t.x); ADDX2(a1, t.y);
                }
            }
        }
        float f0, f1, f2, f3;
        asm("mov.b64 {%0,%1}, %2;" : "=f"(f0), "=f"(f1) : "l"(a0));
        asm("mov.b64 {%0,%1}, %2;" : "=f"(f2), "=f"(f3) : "l"(a1));
        #pragma unroll
        for (int o = 4; o <= 16; o <<= 1) {
            f0 += __shfl_xor_sync(~0u, f0, o);
            f1 += __shfl_xor_sync(~0u, f1, o);
            f2 += __shfl_xor_sync(~0u, f2, o);
            f3 += __shfl_xor_sync(~0u, f3, o);
        }
        if (lane < 4) {
            float di = g_dinv[node];
            float4 bb = ((const float4*)b2)[co];
            float4 o;
            o.x = fmaf(di, f0, bb.x);
            o.y = fmaf(di, f1, bb.y);
            o.z = fmaf(di, f2, bb.z);
            o.w = fmaf(di, f3, bb.w);
            ((float4*)out)[node * 4 + co] = o;
        }
    }
}

extern "C" void kernel_launch(void* const* d_in, const int* in_sizes, int n_in,
                              void* d_out, int out_size) {
    const float* x  = (const float*)d_in[0];
    const void*  ei = d_in[1];
    const float* W1 = (const float*)d_in[2];
    const float* b1 = (const float*)d_in[3];
    const float* W2 = (const float*)d_in[4];
    const float* b2 = (const float*)d_in[5];
    float* out = (float*)d_out;

    int n = in_sizes[0] / C0; if (n > NN) n = NN;
    int E = in_sizes[1] / 2;  if (E > NE) E = NE;
    int nwarps = (n + NPW - 1) / NPW;
    int nblocks = (nwarps + 7) / 8;
    int npairs = (E + 1) / 2;

    k_init<<<(n + 255) / 256, 256>>>((const unsigned*)ei, n, E);
    k_fill<<<(npairs + 255) / 256, 256>>>(ei, E);
    k_scale0<<<(4 * n + 255) / 256, 256>>>(x, n);
    k_gather1<<<nblocks, 256>>>(n);
    k_mlp<<<(n + 255) / 256, 256>>>(W1, b1, W2, n);
    k_layer2<<<nblocks, 256>>>(out, b2, n);
}

// round 13
// speedup vs baseline: 1.1239x; 1.1239x over previous
#include <cuda_runtime.h>
#include <cuda_fp16.h>

// 2-layer GCN. ELL adjacency (cap 128), no padding (R12 lesson: pads cost more
// than predication). R13: software-pipelined node loop — prefetch next node's
// degree + index chunk before current node's reduction, cutting ~250cyc of
// index-load latency out of every per-node critical path.
#define NN 100000
#define NE 3200000
#define C0 13
#define C0P 16
#define C1 32
#define C2 16
#define CAP 128
#define NPW 4   // nodes per warp in gather kernels

#define ADDX2(a, b) asm("add.rn.f32x2 %0, %1, %2;" : "=l"(a) : "l"(a), "l"(b))

__device__ int    g_cur[NN];
__device__ int    g_ell[NN * CAP];   // static zero-init; unused slots stay 0
__device__ float  g_dinv[NN];
__device__ __align__(16) float g_g0[NN * C0P];   // x * dinv, padded 16 ch
__device__ __align__(16) float g_agg[NN * C0P];  // dinv * (sum + self)
__device__ __align__(16) float g_g2[NN * C2];    // (h W2) * dinv
__device__ int    g_odd_nonzero;

// ---------------- init: zero counters + detect int64 vs int32 ----------------
__global__ void k_init(const unsigned* __restrict__ p, int n, int E) {
    int i = blockIdx.x * blockDim.x + threadIdx.x;
    if (i < n) g_cur[i] = 0;
    if (blockIdx.x == 0) {
        if (threadIdx.x == 0) g_odd_nonzero = 0;
        __syncthreads();
        int pairs = E < 2048 ? E : 2048;
        int any = 0;
        for (int j = threadIdx.x; j < pairs; j += blockDim.x)
            if (p[2 * j + 1] != 0u) any = 1;
        if (any) atomicOr(&g_odd_nonzero, 1);
    }
}

// ---------------- build ELL + degree: 2 edges/thread, 16B index loads ----------------
__global__ void k_fill(const void* __restrict__ p, int E) {
    int i = blockIdx.x * blockDim.x + threadIdx.x;   // handles edges 2i, 2i+1
    int e0 = 2 * i;
    if (e0 >= E) return;
    int has2 = (e0 + 1 < E);
    int s0, s1, d0, d1;
    if (g_odd_nonzero == 0) {                        // int64 input
        const long long* q = (const long long*)p;
        longlong2 ts = ((const longlong2*)q)[i];
        longlong2 td = *(const longlong2*)(q + E + e0);
        s0 = (int)ts.x; s1 = (int)ts.y;
        d0 = (int)td.x; d1 = (int)td.y;
    } else {                                          // int32 input
        const int* q = (const int*)p;
        int2 ts = ((const int2*)q)[i];
        int2 td = *(const int2*)(q + E + e0);
        s0 = ts.x; s1 = ts.y;
        d0 = td.x; d1 = td.y;
    }
    int pos0 = atomicAdd(&g_cur[d0], 1);
    if (pos0 < CAP) g_ell[d0 * CAP + pos0] = s0;
    if (has2) {
        int pos1 = atomicAdd(&g_cur[d1], 1);
        if (pos1 < CAP) g_ell[d1 * CAP + pos1] = s1;
    }
}

// ---------------- scale0: g0 = pad16(x) * dinv; also store dinv ----------------
__global__ void k_scale0(const float* __restrict__ x, int n) {
    int t = blockIdx.x * blockDim.x + threadIdx.x;   // 4 threads per node
    int node = t >> 2, co = t & 3;
    if (node >= n) return;
    float di = rsqrtf((float)(g_cur[node] + 1));
    if (co == 0) g_dinv[node] = di;
    float4 v;
    const float* xr = x + node * C0;
    int c = 4 * co;
    v.x = (c     < C0) ? xr[c]     * di : 0.0f;
    v.y = (c + 1 < C0) ? xr[c + 1] * di : 0.0f;
    v.z = (c + 2 < C0) ? xr[c + 2] * di : 0.0f;
    v.w = (c + 3 < C0) ? xr[c + 3] * di : 0.0f;
    ((float4*)g_g0)[node * 4 + co] = v;
}

// ---------------- gather1: agg[node] = dinv * (sum_in g0[src] + g0[node]) ----------------
__global__ void __launch_bounds__(256, 8)
k_gather1(int n) {
    int warp = threadIdx.x >> 5, lane = threadIdx.x & 31;
    int grp = lane >> 2;      // edge subgroup 0..7
    int co  = lane & 3;       // 16B column (4 x float4 = 16 ch)
    const ulonglong2* __restrict__ g0v = (const ulonglong2*)g_g0;  // 4 per row

    int node0 = (blockIdx.x * 8 + warp) * NPW;
    int node1 = node0 + NPW; if (node1 > n) node1 = n;
    if (node0 >= n) return;

    // prologue: prefetch node0's degree + first index chunk
    int deg = g_cur[node0]; if (deg > CAP) deg = CAP;
    int idx = g_ell[node0 * CAP + lane];      // always in-bounds; junk unused

    for (int node = node0; node < node1; node++) {
        // prefetch next node early (independent of this node's chain)
        int degN = 0, idxN = 0;
        if (node + 1 < node1) {
            degN = g_cur[node + 1];
            idxN = g_ell[(node + 1) * CAP + lane];
        }
        unsigned long long a0 = 0ULL, a1 = 0ULL;
        if (grp == 0) {                       // self loop
            ulonglong2 t = g0v[node * 4 + co];
            a0 = t.x; a1 = t.y;
        }
        // chunk 0: preloaded indices
        {
            int m = deg > 32 ? 32 : deg;
            int base = idx * 4;
            if (m == 32) {
                #pragma unroll
                for (int k = 0; k < 4; k++) {
                    int b = __shfl_sync(~0u, base, 8 * k + grp);
                    ulonglong2 t = g0v[b + co];
                    ADDX2(a0, t.x); ADDX2(a1, t.y);
                }
            } else {
                int kmax = (m + 7) >> 3;      // uniform across warp
                for (int k = 0; k < kmax; k++) {
                    int kk = 8 * k + grp;
                    int b = __shfl_sync(~0u, base, kk < m ? kk : 0);
                    if (kk < m) {
                        ulonglong2 t = g0v[b + co];
                        ADDX2(a0, t.x); ADDX2(a1, t.y);
                    }
                }
            }
        }
        // remaining chunks (deg > 32): load indices inline
        const int* __restrict__ row = &g_ell[node * CAP];
        for (int j0 = 32; j0 < deg; j0 += 32) {
            int m = deg - j0; if (m > 32) m = 32;
            int base = row[j0 + lane] * 4;
            if (m == 32) {
                #pragma unroll
                for (int k = 0; k < 4; k++) {
                    int b = __shfl_sync(~0u, base, 8 * k + grp);
                    ulonglong2 t = g0v[b + co];
                    ADDX2(a0, t.x); ADDX2(a1, t.y);
                }
            } else {
                int kmax = (m + 7) >> 3;
                for (int k = 0; k < kmax; k++) {
                    int kk = 8 * k + grp;
                    int b = __shfl_sync(~0u, base, kk < m ? kk : 0);
                    if (kk < m) {
                        ulonglong2 t = g0v[b + co];
                        ADDX2(a0, t.x); ADDX2(a1, t.y);
                    }
                }
            }
        }
        float f0, f1, f2, f3;
        asm("mov.b64 {%0,%1}, %2;" : "=f"(f0), "=f"(f1) : "l"(a0));
        asm("mov.b64 {%0,%1}, %2;" : "=f"(f2), "=f"(f3) : "l"(a1));
        #pragma unroll
        for (int o = 4; o <= 16; o <<= 1) {
            f0 += __shfl_xor_sync(~0u, f0, o);
            f1 += __shfl_xor_sync(~0u, f1, o);
            f2 += __shfl_xor_sync(~0u, f2, o);
            f3 += __shfl_xor_sync(~0u, f3, o);
        }
        if (lane < 4) {
            float di = g_dinv[node];
            float4 a;
            a.x = f0 * di; a.y = f1 * di; a.z = f2 * di; a.w = f3 * di;
            ((float4*)g_agg)[node * 4 + co] = a;
        }
        deg = degN > CAP ? CAP : degN;
        idx = idxN;
    }
}

// ---------------- mlp: g2[node] = dinv * (relu(agg W1 + b1) W2), thread/node ----------------
__global__ void k_mlp(const float* __restrict__ W1, const float* __restrict__ b1,
                      const float* __restrict__ W2, int n) {
    __shared__ __align__(16) float sW1T[C1 * C0P];   // [c][k], k padded to 16, zeros
    __shared__ __align__(16) float sW2[C1 * C2];     // [c][j]
    __shared__ float sb1[C1];
    for (int i = threadIdx.x; i < C1 * C0P; i += blockDim.x) {
        int c = i >> 4, k = i & 15;
        sW1T[i] = (k < C0) ? W1[k * C1 + c] : 0.0f;
    }
    for (int i = threadIdx.x; i < C1 * C2; i += blockDim.x) sW2[i] = W2[i];
    if (threadIdx.x < C1) sb1[threadIdx.x] = b1[threadIdx.x];
    __syncthreads();
    int node = blockIdx.x * blockDim.x + threadIdx.x;
    if (node >= n) return;
    const float4* av = &((const float4*)g_agg)[node * 4];
    float4 A0 = av[0], A1 = av[1], A2 = av[2], A3 = av[3];
    float di = g_dinv[node];
    float o[C2];
    #pragma unroll
    for (int j = 0; j < C2; j++) o[j] = 0.0f;
    #pragma unroll
    for (int c = 0; c < C1; c++) {
        const float4* wt = (const float4*)&sW1T[c * C0P];
        float4 w0 = wt[0], w1 = wt[1], w2 = wt[2], w3 = wt[3];
        float h = sb1[c];
        h = fmaf(A0.x, w0.x, h); h = fmaf(A0.y, w0.y, h);
        h = fmaf(A0.z, w0.z, h); h = fmaf(A0.w, w0.w, h);
        h = fmaf(A1.x, w1.x, h); h = fmaf(A1.y, w1.y, h);
        h = fmaf(A1.z, w1.z, h); h = fmaf(A1.w, w1.w, h);
        h = fmaf(A2.x, w2.x, h); h = fmaf(A2.y, w2.y, h);
        h = fmaf(A2.z, w2.z, h); h = fmaf(A2.w, w2.w, h);
        h = fmaf(A3.x, w3.x, h);
        h = fmaxf(h, 0.0f);
        const float4* wu = (const float4*)&sW2[c * C2];
        float4 u0 = wu[0], u1 = wu[1], u2 = wu[2], u3 = wu[3];
        o[0]  = fmaf(h, u0.x, o[0]);  o[1]  = fmaf(h, u0.y, o[1]);
        o[2]  = fmaf(h, u0.z, o[2]);  o[3]  = fmaf(h, u0.w, o[3]);
        o[4]  = fmaf(h, u1.x, o[4]);  o[5]  = fmaf(h, u1.y, o[5]);
        o[6]  = fmaf(h, u1.z, o[6]);  o[7]  = fmaf(h, u1.w, o[7]);
        o[8]  = fmaf(h, u2.x, o[8]);  o[9]  = fmaf(h, u2.y, o[9]);
        o[10] = fmaf(h, u2.z, o[10]); o[11] = fmaf(h, u2.w, o[11]);
        o[12] = fmaf(h, u3.x, o[12]); o[13] = fmaf(h, u3.y, o[13]);
        o[14] = fmaf(h, u3.z, o[14]); o[15] = fmaf(h, u3.w, o[15]);
    }
    float4* ov = &((float4*)g_g2)[node * 4];
    #pragma unroll
    for (int q = 0; q < 4; q++) {
        float4 r;
        r.x = o[4 * q + 0] * di; r.y = o[4 * q + 1] * di;
        r.z = o[4 * q + 2] * di; r.w = o[4 * q + 3] * di;
        ov[q] = r;
    }
}

// ---------------- layer2 gather + bias -> out (pipelined like gather1) ----------------
__global__ void __launch_bounds__(256, 8)
k_layer2(float* __restrict__ out, const float* __restrict__ b2, int n) {
    int warp = threadIdx.x >> 5, lane = threadIdx.x & 31;
    int grp = lane >> 2;      // edge subgroup 0..7
    int co  = lane & 3;       // 16B column (4 x float4 = 16 ch)
    const ulonglong2* __restrict__ g2v = (const ulonglong2*)g_g2;  // 4 per row

    int node0 = (blockIdx.x * 8 + warp) * NPW;
    int node1 = node0 + NPW; if (node1 > n) node1 = n;
    if (node0 >= n) return;

    int deg = g_cur[node0]; if (deg > CAP) deg = CAP;
    int idx = g_ell[node0 * CAP + lane];

    for (int node = node0; node < node1; node++) {
        int degN = 0, idxN = 0;
        if (node + 1 < node1) {
            degN = g_cur[node + 1];
            idxN = g_ell[(node + 1) * CAP + lane];
        }
        unsigned long long a0 = 0ULL, a1 = 0ULL;
        if (grp == 0) {                       // self loop
            ulonglong2 t = g2v[node * 4 + co];
            a0 = t.x; a1 = t.y;
        }
        {
            int m = deg > 32 ? 32 : deg;
            int base = idx * 4;
            if (m == 32) {
                #pragma unroll
                for (int k = 0; k < 4; k++) {
                    int b = __shfl_sync(~0u, base, 8 * k + grp);
                    ulonglong2 t = g2v[b + co];
                    ADDX2(a0, t.x); ADDX2(a1, t.y);
                }
            } else {
                int kmax = (m + 7) >> 3;
                for (int k = 0; k < kmax; k++) {
                    int kk = 8 * k + grp;
                    int b = __shfl_sync(~0u, base, kk < m ? kk : 0);
                    if (kk < m) {
                        ulonglong2 t = g2v[b + co];
                        ADDX2(a0, t.x); ADDX2(a1, t.y);
                    }
                }
            }
        }
        const int* __restrict__ row = &g_ell[node * CAP];
        for (int j0 = 32; j0 < deg; j0 += 32) {
            int m = deg - j0; if (m > 32) m = 32;
            int base = row[j0 + lane] * 4;
            if (m == 32) {
                #pragma unroll
                for (int k = 0; k < 4; k++) {
                    int b = __shfl_sync(~0u, base, 8 * k + grp);
                    ulonglong2 t = g2v[b + co];
                    ADDX2(a0, t.x); ADDX2(a1, t.y);
                }
            } else {
                int kmax = (m + 7) >> 3;
                for (int k = 0; k < kmax; k++) {
                    int kk = 8 * k + grp;
                    int b = __shfl_sync(~0u, base, kk < m ? kk : 0);
                    if (kk < m) {
                        ulonglong2 t = g2v[b + co];
                        ADDX2(a0, t.x); ADDX2(a1, t.y);
                    }
                }
            }
        }
        float f0, f1, f2, f3;
        asm("mov.b64 {%0,%1}, %2;" : "=f"(f0), "=f"(f1) : "l"(a0));
        asm("mov.b64 {%0,%1}, %2;" : "=f"(f2), "=f"(f3) : "l"(a1));
        #pragma unroll
        for (int o = 4; o <= 16; o <<= 1) {
            f0 += __shfl_xor_sync(~0u, f0, o);
            f1 += __shfl_xor_sync(~0u, f1, o);
            f2 += __shfl_xor_sync(~0u, f2, o);
            f3 += __shfl_xor_sync(~0u, f3, o);
        }
        if (lane < 4) {
            float di = g_dinv[node];
            float4 bb = ((const float4*)b2)[co];
            float4 o;
            o.x = fmaf(di, f0, bb.x);
            o.y = fmaf(di, f1, bb.y);
            o.z = fmaf(di, f2, bb.z);
            o.w = fmaf(di, f3, bb.w);
            ((float4*)out)[node * 4 + co] = o;
        }
        deg = degN > CAP ? CAP : degN;
        idx = idxN;
    }
}

extern "C" void kernel_launch(void* const* d_in, const int* in_sizes, int n_in,
                              void* d_out, int out_size) {
    const float* x  = (const float*)d_in[0];
    const void*  ei = d_in[1];
    const float* W1 = (const float*)d_in[2];
    const float* b1 = (const float*)d_in[3];
    const float* W2 = (const float*)d_in[4];
    const float* b2 = (const float*)d_in[5];
    float* out = (float*)d_out;

    int n = in_sizes[0] / C0; if (n > NN) n = NN;
    int E = in_sizes[1] / 2;  if (E > NE) E = NE;
    int nwarps = (n + NPW - 1) / NPW;
    int nblocks = (nwarps + 7) / 8;
    int npairs = (E + 1) / 2;

    k_init<<<(n + 255) / 256, 256>>>((const unsigned*)ei, n, E);
    k_fill<<<(npairs + 255) / 256, 256>>>(ei, E);
    k_scale0<<<(4 * n + 255) / 256, 256>>>(x, n);
    k_gather1<<<nblocks, 256>>>(n);
    k_mlp<<<(n + 255) / 256, 256>>>(W1, b1, W2, n);
    k_layer2<<<nblocks, 256>>>(out, b2, n);
}